// round 14
// baseline (speedup 1.0000x reference)
#include <cuda_runtime.h>

#define NB    100   // neighbors
#define NF    13    // features
#define ROW4  (NB * NF / 4)      // 325 float4 per batch
#define WPB   4                  // warps per block
#define TPB   (WPB * 32)

// Branch-free Jacobi rotation on symmetric M, accumulating V.
__device__ __forceinline__ void jrot(float M[3][3], float V[3][3], int p, int q) {
    float apq = M[p][q];
    float D   = 0.5f * (M[q][q] - M[p][p]);
    float hyp = sqrtf(fmaf(D, D, fmaf(apq, apq, 1e-38f)));
    float t   = __fdividef(apq, copysignf(fabsf(D) + hyp, D));
    float c   = rsqrtf(fmaf(t, t, 1.0f));
    float s   = t * c;
    float tapq = t * apq;
    M[p][p] -= tapq;
    M[q][q] += tapq;
    M[p][q] = 0.0f; M[q][p] = 0.0f;
    const int r = 3 - p - q;
    float mrp = M[r][p], mrq = M[r][q];
    M[r][p] = fmaf(c, mrp, -s * mrq); M[p][r] = M[r][p];
    M[r][q] = fmaf(s, mrp,  c * mrq); M[q][r] = M[r][q];
#pragma unroll
    for (int i = 0; i < 3; i++) {
        float vip = V[i][p], viq = V[i][q];
        V[i][p] = fmaf(c, vip, -s * viq);
        V[i][q] = fmaf(s, vip,  c * viq);
    }
}

// per-neighbor contribution terms
__device__ __forceinline__ void neigh_terms(const float* __restrict__ r,
                                            float a, float bbias, float shift,
                                            float t[16]) {
    float w = fmaf(a, r[0], bbias);
    w = fmaxf(w, 0.0f) + 1e-8f;
    float v1[3], v2[3], wv2[3];
#pragma unroll
    for (int k = 0; k < 3; k++) {
        v1[k] = fmaf(shift, r[7 + k],  r[1 + k]);
        v2[k] = fmaf(shift, r[10 + k], r[4 + k]);
    }
    t[0] = w;
#pragma unroll
    for (int k = 0; k < 3; k++) {
        t[1 + k] = w * v1[k];
        wv2[k]   = w * v2[k];
        t[4 + k] = wv2[k];
    }
#pragma unroll
    for (int k = 0; k < 3; k++)
#pragma unroll
        for (int j = 0; j < 3; j++)
            t[7 + k * 3 + j] = wv2[k] * v1[j];
}

__global__ void __launch_bounds__(TPB, 10) svd_align_kernel(
    const float* __restrict__ in,
    const float* __restrict__ pa,
    const float* __restrict__ pb,
    const float* __restrict__ pshift,
    float* __restrict__ out,
    int B)
{
    __shared__ float sdat[WPB][NB * NF];
    __shared__ float ssum[WPB][16];    // reduced sums (bit-reversed order) per warp-batch
    __shared__ float rtbuf[WPB][13];   // R(9)+t(3) per warp-batch (padded)

    const int wid  = threadIdx.x >> 5;
    const int lane = threadIdx.x & 31;
    const int wb   = blockIdx.x * WPB + wid;
    const bool ok  = wb < B;           // no early return: __syncthreads below

    const float a     = pa[0];
    const float bbias = pb[0];
    const float shift = pshift[0];

    float* sm = sdat[wid];

    // ---- stage batch row into SMEM via cp.async: zero register footprint ----
    if (ok) {
        const float4* src = (const float4*)(in + (size_t)wb * (NB * NF));
        unsigned smb = (unsigned)__cvta_generic_to_shared(sm);
#pragma unroll
        for (int i = 0; i < 10; i++) {
            int q = i * 32 + lane;
            asm volatile("cp.async.cg.shared.global [%0], [%1], 16;"
                         :: "r"(smb + q * 16), "l"(src + q));
        }
        if (lane < ROW4 - 320) {
            int q = 320 + lane;
            asm volatile("cp.async.cg.shared.global [%0], [%1], 16;"
                         :: "r"(smb + q * 16), "l"(src + q));
        }
        asm volatile("cp.async.commit_group;");
        asm volatile("cp.async.wait_group 0;");
    }
    __syncwarp();

    if (ok) {
        // ---- partials: [w, w*v1(3), w*v2(3), w*v2_k*v1_j(9)]; peel c=0 ----
        float acc[16];
        neigh_terms(&sm[lane * NF], a, bbias, shift, acc);
#pragma unroll
        for (int c = 1; c < 4; c++) {
            int n = c * 32 + lane;
            if (c < 3 || lane < NB - 96) {
                float t[16];
                neigh_terms(&sm[n * NF], a, bbias, shift, t);
#pragma unroll
                for (int k = 0; k < 16; k++) acc[k] += t[k];
            }
        }

        // ---- register-exchange butterfly reduce: 16 vals x 32 lanes ----
        float r8[8];
#pragma unroll
        for (int k = 0; k < 8; k++) {
            float snd = (lane & 1) ? acc[k] : acc[k + 8];
            float rcv = __shfl_xor_sync(0xffffffffu, snd, 1);
            float kep = (lane & 1) ? acc[k + 8] : acc[k];
            r8[k] = kep + rcv;
        }
        float r4[4];
#pragma unroll
        for (int k = 0; k < 4; k++) {
            float snd = (lane & 2) ? r8[k] : r8[k + 4];
            float rcv = __shfl_xor_sync(0xffffffffu, snd, 2);
            float kep = (lane & 2) ? r8[k + 4] : r8[k];
            r4[k] = kep + rcv;
        }
        float r2[2];
#pragma unroll
        for (int k = 0; k < 2; k++) {
            float snd = (lane & 4) ? r4[k] : r4[k + 2];
            float rcv = __shfl_xor_sync(0xffffffffu, snd, 4);
            float kep = (lane & 4) ? r4[k + 2] : r4[k];
            r2[k] = kep + rcv;
        }
        float snd1 = (lane & 8) ? r2[0] : r2[1];
        float rcv1 = __shfl_xor_sync(0xffffffffu, snd1, 8);
        float kep1 = (lane & 8) ? r2[1] : r2[0];
        float red  = kep1 + rcv1;
        red += __shfl_xor_sync(0xffffffffu, red, 16);
        // lane l (0..15): red = sum index rev4(l)
        if (lane < 16) ssum[wid][lane] = red;
    }
    __syncthreads();

    // ---- warp 0: all 4 SVDs convergently on lanes 0/8/16/24 ----
    if (wid == 0 && (lane & 7) == 0) {
        const int bi = lane >> 3;                       // batch-in-block 0..3
        if (blockIdx.x * WPB + bi < B) {
            const float* sp = ssum[bi];                 // f[k] = sp[rev4(k)]
            float f[16];
            f[0]  = sp[0];  f[1]  = sp[8];  f[2]  = sp[4];  f[3]  = sp[12];
            f[4]  = sp[2];  f[5]  = sp[10]; f[6]  = sp[6];  f[7]  = sp[14];
            f[8]  = sp[1];  f[9]  = sp[9];  f[10] = sp[5];  f[11] = sp[13];
            f[12] = sp[3];  f[13] = sp[11]; f[14] = sp[7];  f[15] = sp[15];

            const float inv_w = __fdividef(1.0f, f[0]);
            float v1c[3], v2c[3];
#pragma unroll
            for (int k = 0; k < 3; k++) { v1c[k] = f[1 + k] * inv_w; v2c[k] = f[4 + k] * inv_w; }

            float A[3][3];
#pragma unroll
            for (int k = 0; k < 3; k++)
#pragma unroll
                for (int j = 0; j < 3; j++)
                    A[k][j] = fmaf(-f[4 + k] * inv_w, f[1 + j], f[7 + k * 3 + j]);

            float M[3][3];
#pragma unroll
            for (int i = 0; i < 3; i++)
#pragma unroll
                for (int j = 0; j < 3; j++) {
                    float s = A[0][i] * A[0][j];
                    s = fmaf(A[1][i], A[1][j], s);
                    s = fmaf(A[2][i], A[2][j], s);
                    M[i][j] = s;
                }

            float V[3][3] = {{1,0,0},{0,1,0},{0,0,1}};
#pragma unroll
            for (int sweep = 0; sweep < 3; sweep++) {   // 3 sweeps = verified minimum
                jrot(M, V, 0, 1);
                jrot(M, V, 0, 2);
                jrot(M, V, 1, 2);
            }

            // branch-free descending eigen-sort (det fix lands on smallest dir)
            float e0 = M[0][0], e1 = M[1][1], e2 = M[2][2];
            float c0[3] = { V[0][0], V[1][0], V[2][0] };
            float c1[3] = { V[0][1], V[1][1], V[2][1] };
            float c2[3] = { V[0][2], V[1][2], V[2][2] };
            {
                bool sw = e0 < e1;
                float te = sw ? e1 : e0; e1 = sw ? e0 : e1; e0 = te;
#pragma unroll
                for (int i = 0; i < 3; i++) { float tv = sw ? c1[i] : c0[i]; c1[i] = sw ? c0[i] : c1[i]; c0[i] = tv; }
            }
            {
                bool sw = e1 < e2;
                float te = sw ? e2 : e1; e2 = sw ? e1 : e2; e1 = te;
#pragma unroll
                for (int i = 0; i < 3; i++) { float tv = sw ? c2[i] : c1[i]; c2[i] = sw ? c1[i] : c2[i]; c1[i] = tv; }
            }
            {
                bool sw = e0 < e1;
                float te = sw ? e1 : e0; e1 = sw ? e0 : e1; e0 = te;
#pragma unroll
                for (int i = 0; i < 3; i++) { float tv = sw ? c1[i] : c0[i]; c1[i] = sw ? c0[i] : c1[i]; c0[i] = tv; }
            }

            // U: u0 = norm(A c0); u1 = orth-norm(A c1); u2 = u0 x u1
            float u0[3], u1[3], u2[3];
#pragma unroll
            for (int i = 0; i < 3; i++) {
                u0[i] = A[i][0] * c0[0] + A[i][1] * c0[1] + A[i][2] * c0[2];
                u1[i] = A[i][0] * c1[0] + A[i][1] * c1[1] + A[i][2] * c1[2];
            }
            float n0 = rsqrtf(fmaf(u0[0], u0[0], fmaf(u0[1], u0[1], fmaf(u0[2], u0[2], 1e-30f))));
#pragma unroll
            for (int i = 0; i < 3; i++) u0[i] *= n0;
            float d01 = u0[0]*u1[0] + u0[1]*u1[1] + u0[2]*u1[2];
#pragma unroll
            for (int i = 0; i < 3; i++) u1[i] = fmaf(-d01, u0[i], u1[i]);
            float n1 = rsqrtf(fmaf(u1[0], u1[0], fmaf(u1[1], u1[1], fmaf(u1[2], u1[2], 1e-30f))));
#pragma unroll
            for (int i = 0; i < 3; i++) u1[i] *= n1;
            u2[0] = u0[1]*u1[2] - u0[2]*u1[1];
            u2[1] = u0[2]*u1[0] - u0[0]*u1[2];
            u2[2] = u0[0]*u1[1] - u0[1]*u1[0];

            float detV =
                c0[0] * (c1[1]*c2[2] - c1[2]*c2[1]) -
                c1[0] * (c0[1]*c2[2] - c0[2]*c2[1]) +
                c2[0] * (c0[1]*c1[2] - c0[2]*c1[1]);
            float d3 = (detV > 0.0f) ? 1.0f : -1.0f;

            float c2d[3] = { d3 * c2[0], d3 * c2[1], d3 * c2[2] };
            float* rts = rtbuf[bi];
#pragma unroll
            for (int i = 0; i < 3; i++) {
                float Ri0 = c0[i]*u0[0] + c1[i]*u1[0] + c2d[i]*u2[0];
                float Ri1 = c0[i]*u0[1] + c1[i]*u1[1] + c2d[i]*u2[1];
                float Ri2 = c0[i]*u0[2] + c1[i]*u1[2] + c2d[i]*u2[2];
                rts[i * 3 + 0] = Ri0;
                rts[i * 3 + 1] = Ri1;
                rts[i * 3 + 2] = Ri2;
                rts[9 + i] = v1c[i] - (Ri0 * v2c[0] + Ri1 * v2c[1] + Ri2 * v2c[2]);
            }
        }
    }
    __syncthreads();

    // ---- apply: one neighbor per lane, 3x STG.64; R,t via LDS broadcast ----
    if (ok) {
        float Rt[12];
#pragma unroll
        for (int k = 0; k < 12; k++) Rt[k] = rtbuf[wid][k];

        float* ob = out + (size_t)wb * (NB * 6);
#pragma unroll
        for (int c = 0; c < 4; c++) {
            int n = c * 32 + lane;
            if (c < 3 || lane < NB - 96) {
                const float* row = &sm[n * NF];
                float x0 = row[4],  x1 = row[5],  x2 = row[6];
                float m0 = row[10], m1 = row[11], m2 = row[12];
                float2 o0, o1, o2;
                o0.x = fmaf(Rt[0], x0, fmaf(Rt[1], x1, fmaf(Rt[2], x2, Rt[9])));
                o0.y = fmaf(Rt[3], x0, fmaf(Rt[4], x1, fmaf(Rt[5], x2, Rt[10])));
                o1.x = fmaf(Rt[6], x0, fmaf(Rt[7], x1, fmaf(Rt[8], x2, Rt[11])));
                o1.y = fmaf(Rt[0], m0, fmaf(Rt[1], m1, Rt[2] * m2));
                o2.x = fmaf(Rt[3], m0, fmaf(Rt[4], m1, Rt[5] * m2));
                o2.y = fmaf(Rt[6], m0, fmaf(Rt[7], m1, Rt[8] * m2));
                float2* op = (float2*)(ob + n * 6);
                op[0] = o0; op[1] = o1; op[2] = o2;
            }
        }
    }
}

extern "C" void kernel_launch(void* const* d_in, const int* in_sizes, int n_in,
                              void* d_out, int out_size) {
    const float* net   = (const float*)d_in[0];
    const float* a     = (const float*)d_in[1];
    const float* b     = (const float*)d_in[2];
    const float* shift = (const float*)d_in[3];
    float* out = (float*)d_out;

    int B = in_sizes[0] / (NB * NF);   // 100000
    int grid = (B + WPB - 1) / WPB;
    svd_align_kernel<<<grid, TPB>>>(net, a, b, shift, out, B);
}

// round 15
// speedup vs baseline: 1.0176x; 1.0176x over previous
#include <cuda_runtime.h>

#define NB    100   // neighbors
#define NF    13    // features
#define ROW4  (NB * NF / 4)      // 325 float4 per batch
#define WPB   4                  // warps per block
#define TPB   (WPB * 32)

// Branch-free Jacobi rotation on symmetric M, accumulating V.
__device__ __forceinline__ void jrot(float M[3][3], float V[3][3], int p, int q) {
    float apq = M[p][q];
    float D   = 0.5f * (M[q][q] - M[p][p]);
    float hyp = sqrtf(fmaf(D, D, fmaf(apq, apq, 1e-38f)));
    float t   = __fdividef(apq, copysignf(fabsf(D) + hyp, D));
    float c   = rsqrtf(fmaf(t, t, 1.0f));
    float s   = t * c;
    float tapq = t * apq;
    M[p][p] -= tapq;
    M[q][q] += tapq;
    M[p][q] = 0.0f; M[q][p] = 0.0f;
    const int r = 3 - p - q;
    float mrp = M[r][p], mrq = M[r][q];
    M[r][p] = fmaf(c, mrp, -s * mrq); M[p][r] = M[r][p];
    M[r][q] = fmaf(s, mrp,  c * mrq); M[q][r] = M[r][q];
#pragma unroll
    for (int i = 0; i < 3; i++) {
        float vip = V[i][p], viq = V[i][q];
        V[i][p] = fmaf(c, vip, -s * viq);
        V[i][q] = fmaf(s, vip,  c * viq);
    }
}

// per-neighbor contribution terms
__device__ __forceinline__ void neigh_terms(const float* __restrict__ r,
                                            float a, float bbias, float shift,
                                            float t[16]) {
    float w = fmaf(a, r[0], bbias);
    w = fmaxf(w, 0.0f) + 1e-8f;
    float v1[3], v2[3], wv2[3];
#pragma unroll
    for (int k = 0; k < 3; k++) {
        v1[k] = fmaf(shift, r[7 + k],  r[1 + k]);
        v2[k] = fmaf(shift, r[10 + k], r[4 + k]);
    }
    t[0] = w;
#pragma unroll
    for (int k = 0; k < 3; k++) {
        t[1 + k] = w * v1[k];
        wv2[k]   = w * v2[k];
        t[4 + k] = wv2[k];
    }
#pragma unroll
    for (int k = 0; k < 3; k++)
#pragma unroll
        for (int j = 0; j < 3; j++)
            t[7 + k * 3 + j] = wv2[k] * v1[j];
}

// streaming (evict-first) 8-byte store: output has zero reuse
__device__ __forceinline__ void stg_cs_v2(float* p, float x, float y) {
    asm volatile("st.global.cs.v2.f32 [%0], {%1, %2};" :: "l"(p), "f"(x), "f"(y) : "memory");
}

__global__ void __launch_bounds__(TPB, 10) svd_align_kernel(
    const float* __restrict__ in,
    const float* __restrict__ pa,
    const float* __restrict__ pb,
    const float* __restrict__ pshift,
    float* __restrict__ out,
    int B)
{
    __shared__ float sdat[WPB][NB * NF];
    __shared__ float ssum[WPB][16];    // butterfly results bounce (bit-reversed order)

    const int wid  = threadIdx.x >> 5;
    const int lane = threadIdx.x & 31;
    const int wb   = blockIdx.x * WPB + wid;
    if (wb >= B) return;

    const float a     = pa[0];
    const float bbias = pb[0];
    const float shift = pshift[0];

    float* sm = sdat[wid];

    // ---- stage batch row into SMEM via cp.async: zero register footprint ----
    {
        const float4* src = (const float4*)(in + (size_t)wb * (NB * NF));
        unsigned smb = (unsigned)__cvta_generic_to_shared(sm);
#pragma unroll
        for (int i = 0; i < 10; i++) {
            int q = i * 32 + lane;
            asm volatile("cp.async.cg.shared.global [%0], [%1], 16;"
                         :: "r"(smb + q * 16), "l"(src + q));
        }
        if (lane < ROW4 - 320) {
            int q = 320 + lane;
            asm volatile("cp.async.cg.shared.global [%0], [%1], 16;"
                         :: "r"(smb + q * 16), "l"(src + q));
        }
        asm volatile("cp.async.commit_group;");
        asm volatile("cp.async.wait_group 0;");
    }
    __syncwarp();

    // ---- partials: [w, w*v1(3), w*v2(3), w*v2_k*v1_j(9)]; peel c=0 ----
    float acc[16];
    neigh_terms(&sm[lane * NF], a, bbias, shift, acc);

#pragma unroll
    for (int c = 1; c < 4; c++) {
        int n = c * 32 + lane;
        if (c < 3 || lane < NB - 96) {
            float t[16];
            neigh_terms(&sm[n * NF], a, bbias, shift, t);
#pragma unroll
            for (int k = 0; k < 16; k++) acc[k] += t[k];
        }
    }

    // ---- register-exchange butterfly reduce: 16 vals x 32 lanes ----
    float r8[8];
#pragma unroll
    for (int k = 0; k < 8; k++) {
        float snd = (lane & 1) ? acc[k] : acc[k + 8];
        float rcv = __shfl_xor_sync(0xffffffffu, snd, 1);
        float kep = (lane & 1) ? acc[k + 8] : acc[k];
        r8[k] = kep + rcv;
    }
    float r4[4];
#pragma unroll
    for (int k = 0; k < 4; k++) {
        float snd = (lane & 2) ? r8[k] : r8[k + 4];
        float rcv = __shfl_xor_sync(0xffffffffu, snd, 2);
        float kep = (lane & 2) ? r8[k + 4] : r8[k];
        r4[k] = kep + rcv;
    }
    float r2[2];
#pragma unroll
    for (int k = 0; k < 2; k++) {
        float snd = (lane & 4) ? r4[k] : r4[k + 2];
        float rcv = __shfl_xor_sync(0xffffffffu, snd, 4);
        float kep = (lane & 4) ? r4[k + 2] : r4[k];
        r2[k] = kep + rcv;
    }
    float snd1 = (lane & 8) ? r2[0] : r2[1];
    float rcv1 = __shfl_xor_sync(0xffffffffu, snd1, 8);
    float kep1 = (lane & 8) ? r2[1] : r2[0];
    float red  = kep1 + rcv1;
    red += __shfl_xor_sync(0xffffffffu, red, 16);
    // lane l (0..15): red = sum index rev4(l). Bounce via SMEM.
    if (lane < 16) ssum[wid][lane] = red;
    __syncwarp();

    // ---- lane 0: 3x3 weighted-Kabsch SVD ----
    float R00=0, R01=0, R02=0, R10=0, R11=0, R12=0, R20=0, R21=0, R22=0, t0=0, t1=0, t2=0;
    if (lane == 0) {
        const float* sp = ssum[wid];   // f[k] = sp[rev4(k)]
        float f[16];
        f[0]  = sp[0];  f[1]  = sp[8];  f[2]  = sp[4];  f[3]  = sp[12];
        f[4]  = sp[2];  f[5]  = sp[10]; f[6]  = sp[6];  f[7]  = sp[14];
        f[8]  = sp[1];  f[9]  = sp[9];  f[10] = sp[5];  f[11] = sp[13];
        f[12] = sp[3];  f[13] = sp[11]; f[14] = sp[7];  f[15] = sp[15];

        const float inv_w = __fdividef(1.0f, f[0]);
        float v1c[3], v2c[3];
#pragma unroll
        for (int k = 0; k < 3; k++) { v1c[k] = f[1 + k] * inv_w; v2c[k] = f[4 + k] * inv_w; }

        float A[3][3];
#pragma unroll
        for (int k = 0; k < 3; k++)
#pragma unroll
            for (int j = 0; j < 3; j++)
                A[k][j] = fmaf(-f[4 + k] * inv_w, f[1 + j], f[7 + k * 3 + j]);

        float M[3][3];
#pragma unroll
        for (int i = 0; i < 3; i++)
#pragma unroll
            for (int j = 0; j < 3; j++) {
                float s = A[0][i] * A[0][j];
                s = fmaf(A[1][i], A[1][j], s);
                s = fmaf(A[2][i], A[2][j], s);
                M[i][j] = s;
            }

        float V[3][3] = {{1,0,0},{0,1,0},{0,0,1}};
#pragma unroll
        for (int sweep = 0; sweep < 3; sweep++) {   // 3 sweeps = verified minimum
            jrot(M, V, 0, 1);
            jrot(M, V, 0, 2);
            jrot(M, V, 1, 2);
        }

        // branch-free descending eigen-sort (det fix lands on smallest dir)
        float e0 = M[0][0], e1 = M[1][1], e2 = M[2][2];
        float c0[3] = { V[0][0], V[1][0], V[2][0] };
        float c1[3] = { V[0][1], V[1][1], V[2][1] };
        float c2[3] = { V[0][2], V[1][2], V[2][2] };
        {
            bool sw = e0 < e1;
            float te = sw ? e1 : e0; e1 = sw ? e0 : e1; e0 = te;
#pragma unroll
            for (int i = 0; i < 3; i++) { float tv = sw ? c1[i] : c0[i]; c1[i] = sw ? c0[i] : c1[i]; c0[i] = tv; }
        }
        {
            bool sw = e1 < e2;
            float te = sw ? e2 : e1; e2 = sw ? e1 : e2; e1 = te;
#pragma unroll
            for (int i = 0; i < 3; i++) { float tv = sw ? c2[i] : c1[i]; c2[i] = sw ? c1[i] : c2[i]; c1[i] = tv; }
        }
        {
            bool sw = e0 < e1;
            float te = sw ? e1 : e0; e1 = sw ? e0 : e1; e0 = te;
#pragma unroll
            for (int i = 0; i < 3; i++) { float tv = sw ? c1[i] : c0[i]; c1[i] = sw ? c0[i] : c1[i]; c0[i] = tv; }
        }

        // U: u0 = norm(A c0); u1 = orth-norm(A c1); u2 = u0 x u1
        float u0[3], u1[3], u2[3];
#pragma unroll
        for (int i = 0; i < 3; i++) {
            u0[i] = A[i][0] * c0[0] + A[i][1] * c0[1] + A[i][2] * c0[2];
            u1[i] = A[i][0] * c1[0] + A[i][1] * c1[1] + A[i][2] * c1[2];
        }
        float n0 = rsqrtf(fmaf(u0[0], u0[0], fmaf(u0[1], u0[1], fmaf(u0[2], u0[2], 1e-30f))));
#pragma unroll
        for (int i = 0; i < 3; i++) u0[i] *= n0;
        float d01 = u0[0]*u1[0] + u0[1]*u1[1] + u0[2]*u1[2];
#pragma unroll
        for (int i = 0; i < 3; i++) u1[i] = fmaf(-d01, u0[i], u1[i]);
        float n1 = rsqrtf(fmaf(u1[0], u1[0], fmaf(u1[1], u1[1], fmaf(u1[2], u1[2], 1e-30f))));
#pragma unroll
        for (int i = 0; i < 3; i++) u1[i] *= n1;
        u2[0] = u0[1]*u1[2] - u0[2]*u1[1];
        u2[1] = u0[2]*u1[0] - u0[0]*u1[2];
        u2[2] = u0[0]*u1[1] - u0[1]*u1[0];

        float detV =
            c0[0] * (c1[1]*c2[2] - c1[2]*c2[1]) -
            c1[0] * (c0[1]*c2[2] - c0[2]*c2[1]) +
            c2[0] * (c0[1]*c1[2] - c0[2]*c1[1]);
        float d3 = (detV > 0.0f) ? 1.0f : -1.0f;

        float c2d[3] = { d3 * c2[0], d3 * c2[1], d3 * c2[2] };
        R00 = c0[0]*u0[0] + c1[0]*u1[0] + c2d[0]*u2[0];
        R01 = c0[0]*u0[1] + c1[0]*u1[1] + c2d[0]*u2[1];
        R02 = c0[0]*u0[2] + c1[0]*u1[2] + c2d[0]*u2[2];
        R10 = c0[1]*u0[0] + c1[1]*u1[0] + c2d[1]*u2[0];
        R11 = c0[1]*u0[1] + c1[1]*u1[1] + c2d[1]*u2[1];
        R12 = c0[1]*u0[2] + c1[1]*u1[2] + c2d[1]*u2[2];
        R20 = c0[2]*u0[0] + c1[2]*u1[0] + c2d[2]*u2[0];
        R21 = c0[2]*u0[1] + c1[2]*u1[1] + c2d[2]*u2[1];
        R22 = c0[2]*u0[2] + c1[2]*u1[2] + c2d[2]*u2[2];
        t0 = v1c[0] - (R00*v2c[0] + R01*v2c[1] + R02*v2c[2]);
        t1 = v1c[1] - (R10*v2c[0] + R11*v2c[1] + R12*v2c[2]);
        t2 = v1c[2] - (R20*v2c[0] + R21*v2c[1] + R22*v2c[2]);
    }

    // broadcast R, t
    float Rt[12];
    Rt[0]=R00; Rt[1]=R01; Rt[2]=R02; Rt[3]=R10; Rt[4]=R11; Rt[5]=R12;
    Rt[6]=R20; Rt[7]=R21; Rt[8]=R22; Rt[9]=t0; Rt[10]=t1; Rt[11]=t2;
#pragma unroll
    for (int k = 0; k < 12; k++) Rt[k] = __shfl_sync(0xffffffffu, Rt[k], 0);

    // ---- apply: one neighbor per lane, 3x streaming STG.64 ----
    float* ob = out + (size_t)wb * (NB * 6);
#pragma unroll
    for (int c = 0; c < 4; c++) {
        int n = c * 32 + lane;
        if (c < 3 || lane < NB - 96) {
            const float* row = &sm[n * NF];
            float x0 = row[4],  x1 = row[5],  x2 = row[6];
            float m0 = row[10], m1 = row[11], m2 = row[12];
            float* op = ob + n * 6;
            stg_cs_v2(op,
                fmaf(Rt[0], x0, fmaf(Rt[1], x1, fmaf(Rt[2], x2, Rt[9]))),
                fmaf(Rt[3], x0, fmaf(Rt[4], x1, fmaf(Rt[5], x2, Rt[10]))));
            stg_cs_v2(op + 2,
                fmaf(Rt[6], x0, fmaf(Rt[7], x1, fmaf(Rt[8], x2, Rt[11]))),
                fmaf(Rt[0], m0, fmaf(Rt[1], m1, Rt[2] * m2)));
            stg_cs_v2(op + 4,
                fmaf(Rt[3], m0, fmaf(Rt[4], m1, Rt[5] * m2)),
                fmaf(Rt[6], m0, fmaf(Rt[7], m1, Rt[8] * m2)));
        }
    }
}

extern "C" void kernel_launch(void* const* d_in, const int* in_sizes, int n_in,
                              void* d_out, int out_size) {
    const float* net   = (const float*)d_in[0];
    const float* a     = (const float*)d_in[1];
    const float* b     = (const float*)d_in[2];
    const float* shift = (const float*)d_in[3];
    float* out = (float*)d_out;

    int B = in_sizes[0] / (NB * NF);   // 100000
    int grid = (B + WPB - 1) / WPB;
    svd_align_kernel<<<grid, TPB>>>(net, a, b, shift, out, B);
}